// round 10
// baseline (speedup 1.0000x reference)
#include <cuda_runtime.h>
#include <cuda_fp16.h>
#include <math.h>
#include <stdint.h>

// ---------------- problem constants ----------------
#define BATCH 4
#define IMGH  64
#define IMGW  64
#define CDIM  768
#define WS    14
#define TOK   196
#define NH    12
#define HD    64
#define NWH   5
#define NWW   5
#define BW    100
#define ROWS_WIN 19600
#define ROWS_IMG 16384
#define QKVN  2304
#define FFN   3072

// ---------------- scratch ----------------
__device__ __half g_win[(size_t)ROWS_WIN * CDIM];
__device__ __half g_qkv[(size_t)ROWS_WIN * QKVN];
__device__ __half g_att[(size_t)ROWS_WIN * CDIM];
__device__ float  g_x2 [(size_t)ROWS_IMG * CDIM];
__device__ __half g_yln[(size_t)ROWS_IMG * CDIM];
__device__ __half g_y1 [(size_t)ROWS_IMG * FFN];
__device__ __half g_wqkv[(size_t)CDIM * QKVN];
__device__ __half g_wproj[(size_t)CDIM * CDIM];
__device__ __half g_wfc1[(size_t)CDIM * FFN];
__device__ __half g_wfc2[(size_t)FFN * CDIM];

// ---------------- helpers ----------------
__device__ __forceinline__ uint32_t smem_u32(const void* p) {
    uint32_t a;
    asm("{ .reg .u64 t; cvta.to.shared.u64 t, %1; cvt.u32.u64 %0, t; }" : "=r"(a) : "l"(p));
    return a;
}
__device__ __forceinline__ void cp16(void* sdst, const void* gsrc, int bytes) {
    uint32_t sa = smem_u32(sdst);
    asm volatile("cp.async.cg.shared.global [%0], [%1], 16, %2;" :: "r"(sa), "l"(gsrc), "r"(bytes));
}
#define CP_COMMIT() asm volatile("cp.async.commit_group;")

__device__ __forceinline__ void mma_f16(float c[4], const uint32_t a[4], const uint32_t b[2]) {
    asm volatile(
        "mma.sync.aligned.m16n8k16.row.col.f32.f16.f16.f32 "
        "{%0,%1,%2,%3}, {%4,%5,%6,%7}, {%8,%9}, {%0,%1,%2,%3};"
        : "+f"(c[0]), "+f"(c[1]), "+f"(c[2]), "+f"(c[3])
        : "r"(a[0]), "r"(a[1]), "r"(a[2]), "r"(a[3]), "r"(b[0]), "r"(b[1]));
}
__device__ __forceinline__ void ldmatrix_x4(uint32_t r[4], uint32_t addr) {
    asm volatile("ldmatrix.sync.aligned.m8n8.x4.shared.b16 {%0,%1,%2,%3}, [%4];"
                 : "=r"(r[0]), "=r"(r[1]), "=r"(r[2]), "=r"(r[3]) : "r"(addr));
}
__device__ __forceinline__ void ldmatrix_x2(uint32_t r[2], uint32_t addr) {
    asm volatile("ldmatrix.sync.aligned.m8n8.x2.shared.b16 {%0,%1}, [%2];"
                 : "=r"(r[0]), "=r"(r[1]) : "r"(addr));
}
__device__ __forceinline__ void ldmatrix_x2_trans(uint32_t r[2], uint32_t addr) {
    asm volatile("ldmatrix.sync.aligned.m8n8.x2.trans.shared.b16 {%0,%1}, [%2];"
                 : "=r"(r[0]), "=r"(r[1]) : "r"(addr));
}

// ---------------- all weights -> half2 k-pair interleaved ----------------
#define W1T ((CDIM / 2) * QKVN)
#define W2T ((CDIM / 2) * CDIM)
#define W3T ((CDIM / 2) * FFN)
#define W4T ((FFN / 2) * CDIM)
__global__ void w2h_all_kernel(const float* __restrict__ wq, const float* __restrict__ wp,
                               const float* __restrict__ w1, const float* __restrict__ w2,
                               __half* __restrict__ oq, __half* __restrict__ op,
                               __half* __restrict__ o1, __half* __restrict__ o2) {
    int idx = blockIdx.x * blockDim.x + threadIdx.x;
    const float* in; __half* out; int Nd, local;
    if (idx < W1T)                    { in = wq; out = oq; Nd = QKVN; local = idx; }
    else if (idx < W1T + W2T)         { in = wp; out = op; Nd = CDIM; local = idx - W1T; }
    else if (idx < W1T + W2T + W3T)   { in = w1; out = o1; Nd = FFN;  local = idx - W1T - W2T; }
    else if (idx < W1T + W2T + W3T + W4T) { in = w2; out = o2; Nd = CDIM; local = idx - W1T - W2T - W3T; }
    else return;
    int kp = local / Nd, n = local % Nd;
    float a = in[(size_t)(2 * kp) * Nd + n];
    float b = in[(size_t)(2 * kp + 1) * Nd + n];
    ((__half2*)out)[local] = __floats2half2_rn(a, b);
}

// ---------------- LN1 + window partition -> half ----------------
__global__ void ln1_win_kernel(const float* __restrict__ x,
                               const float* __restrict__ g,
                               const float* __restrict__ b,
                               __half* __restrict__ out_) {
    int warp = (blockIdx.x * blockDim.x + threadIdx.x) >> 5;
    int lane = threadIdx.x & 31;
    if (warp >= ROWS_WIN) return;
    int r = warp;
    int bw = r / TOK, t = r % TOK;
    int bb = bw / (NWH * NWW), rem = bw % (NWH * NWW);
    int wh = rem / NWW, ww = rem % NWW;
    int i = t / WS, j = t % WS;
    int h = wh * WS + i, w = ww * WS + j;
    __half* out = out_ + (size_t)r * CDIM;
    if (h >= IMGH || w >= IMGW) {
        uint2 z = make_uint2(0u, 0u);
        #pragma unroll
        for (int q = 0; q < 6; q++) *(uint2*)(out + lane * 4 + q * 128) = z;
        return;
    }
    const float* row = x + ((size_t)(bb * IMGH + h) * IMGW + w) * CDIM;
    float v[24];
    float s = 0.f;
    #pragma unroll
    for (int q = 0; q < 6; q++) {
        float4 f = *(const float4*)(row + lane * 4 + q * 128);
        v[q*4+0] = f.x; v[q*4+1] = f.y; v[q*4+2] = f.z; v[q*4+3] = f.w;
        s += f.x + f.y + f.z + f.w;
    }
    #pragma unroll
    for (int o = 16; o > 0; o >>= 1) s += __shfl_xor_sync(0xffffffffu, s, o);
    float mean = s * (1.0f / CDIM);
    float ss = 0.f;
    #pragma unroll
    for (int q = 0; q < 24; q++) { float d = v[q] - mean; ss += d * d; }
    #pragma unroll
    for (int o = 16; o > 0; o >>= 1) ss += __shfl_xor_sync(0xffffffffu, ss, o);
    float rstd = rsqrtf(ss * (1.0f / CDIM) + 1e-6f);
    #pragma unroll
    for (int q = 0; q < 6; q++) {
        int c = lane * 4 + q * 128;
        float4 gg = *(const float4*)(g + c);
        float4 bb4 = *(const float4*)(b + c);
        __half2 h0 = __floats2half2_rn((v[q*4+0] - mean) * rstd * gg.x + bb4.x,
                                       (v[q*4+1] - mean) * rstd * gg.y + bb4.y);
        __half2 h1 = __floats2half2_rn((v[q*4+2] - mean) * rstd * gg.z + bb4.z,
                                       (v[q*4+3] - mean) * rstd * gg.w + bb4.w);
        *(__half2*)(out + c) = h0;
        *(__half2*)(out + c + 2) = h1;
    }
}

// ---------------- LN2 -> half ----------------
__global__ void ln2_kernel(const float* __restrict__ x,
                           const float* __restrict__ g,
                           const float* __restrict__ b,
                           __half* __restrict__ out_) {
    int warp = (blockIdx.x * blockDim.x + threadIdx.x) >> 5;
    int lane = threadIdx.x & 31;
    if (warp >= ROWS_IMG) return;
    const float* row = x + (size_t)warp * CDIM;
    __half* out = out_ + (size_t)warp * CDIM;
    float v[24];
    float s = 0.f;
    #pragma unroll
    for (int q = 0; q < 6; q++) {
        float4 f = *(const float4*)(row + lane * 4 + q * 128);
        v[q*4+0] = f.x; v[q*4+1] = f.y; v[q*4+2] = f.z; v[q*4+3] = f.w;
        s += f.x + f.y + f.z + f.w;
    }
    #pragma unroll
    for (int o = 16; o > 0; o >>= 1) s += __shfl_xor_sync(0xffffffffu, s, o);
    float mean = s * (1.0f / CDIM);
    float ss = 0.f;
    #pragma unroll
    for (int q = 0; q < 24; q++) { float d = v[q] - mean; ss += d * d; }
    #pragma unroll
    for (int o = 16; o > 0; o >>= 1) ss += __shfl_xor_sync(0xffffffffu, ss, o);
    float rstd = rsqrtf(ss * (1.0f / CDIM) + 1e-6f);
    #pragma unroll
    for (int q = 0; q < 6; q++) {
        int c = lane * 4 + q * 128;
        float4 gg = *(const float4*)(g + c);
        float4 bb4 = *(const float4*)(b + c);
        __half2 h0 = __floats2half2_rn((v[q*4+0] - mean) * rstd * gg.x + bb4.x,
                                       (v[q*4+1] - mean) * rstd * gg.y + bb4.y);
        __half2 h1 = __floats2half2_rn((v[q*4+2] - mean) * rstd * gg.z + bb4.z,
                                       (v[q*4+3] - mean) * rstd * gg.w + bb4.w);
        *(__half2*)(out + c) = h0;
        *(__half2*)(out + c + 2) = h1;
    }
}

// ---------------- FP16 mma.sync GEMM (k-slab 64, 3-stage, single-sync) ----------------
#define ASTRH 72
#define BSTR2 136
#define A_STAGE_B (128 * ASTRH * 2)
#define B_STAGE_B (32 * BSTR2 * 4)
#define NSTAGE 3
#define GEMM_SMEM_BYTES (NSTAGE * (A_STAGE_B + B_STAGE_B))

template<int EPI>
__global__ __launch_bounds__(256, 2)
void hgemm(const __half* __restrict__ A, const __half* __restrict__ B2,
           const float* __restrict__ bias, const float* __restrict__ R,
           void* __restrict__ Cc, int M, int N, int K) {
    extern __shared__ char smc[];
    __half* As = (__half*)smc;
    __half2* Bs = (__half2*)(smc + NSTAGE * A_STAGE_B);
    uint32_t As_u32 = smem_u32(As);

    int tid = threadIdx.x, wid = tid >> 5, lane = tid & 31;
    int g = lane >> 2, c = lane & 3;
    int mw = (wid >> 2) * 64, nw = (wid & 3) * 32;
    int m0 = blockIdx.y * 128, n0 = blockIdx.x * 128;

    float acc[4][4][4];
    #pragma unroll
    for (int i = 0; i < 4; i++)
        #pragma unroll
        for (int j = 0; j < 4; j++)
            #pragma unroll
            for (int q = 0; q < 4; q++) acc[i][j][q] = 0.f;

    int arow = tid >> 2, achk = (tid & 3) * 16;
    int bkrow = tid >> 3, bseg = (tid & 7) * 16;

    uint32_t a_lm_off = (uint32_t)((mw + (lane & 15)) * ASTRH + (lane >> 4) * 8) * 2;

    auto loadStage = [&](int t) {
        int st = t % NSTAGE;
        __half* Ad = As + (size_t)st * 128 * ASTRH;
        #pragma unroll
        for (int p = 0; p < 2; p++) {
            int r = arow + p * 64;
            int m = m0 + r;
            bool v = m < M;
            const __half* src = v ? (A + (size_t)m * K + t * 64 + achk) : A;
            cp16(Ad + r * ASTRH + achk,     src,             v ? 16 : 0);
            cp16(Ad + r * ASTRH + achk + 8, v ? src + 8 : A, v ? 16 : 0);
        }
        __half2* Bd = Bs + (size_t)st * 32 * BSTR2;
        const __half2* bsrc = (const __half2*)B2 + (size_t)(t * 32 + bkrow) * N + n0 + bseg;
        #pragma unroll
        for (int i = 0; i < 4; i++)
            cp16(Bd + bkrow * BSTR2 + bseg + 4 * i, bsrc + 4 * i, 16);
        CP_COMMIT();
    };

    int nk = K / 64;
    #pragma unroll
    for (int t = 0; t < NSTAGE - 1; t++) loadStage(t);

    for (int t = 0; t < nk; t++) {
        asm volatile("cp.async.wait_group %0;" :: "n"(NSTAGE - 2) : "memory");
        __syncthreads();
        if (t + NSTAGE - 1 < nk) loadStage(t + NSTAGE - 1);
        else CP_COMMIT();
        uint32_t a_base = As_u32 + (uint32_t)((t % NSTAGE) * A_STAGE_B) + a_lm_off;
        const __half2* b_s = Bs + (size_t)(t % NSTAGE) * 32 * BSTR2;
        #pragma unroll
        for (int kk = 0; kk < 4; kk++) {
            uint32_t af[4][4], bf[4][2];
            #pragma unroll
            for (int tm = 0; tm < 4; tm++)
                ldmatrix_x4(af[tm], a_base + (uint32_t)(tm * 16 * ASTRH + kk * 16) * 2);
            #pragma unroll
            for (int tn = 0; tn < 4; tn++) {
                const __half2* bp = b_s + (kk * 8 + c) * BSTR2 + nw + tn * 8 + g;
                bf[tn][0] = *(const uint32_t*)(bp);
                bf[tn][1] = *(const uint32_t*)(bp + 4 * BSTR2);
            }
            #pragma unroll
            for (int tm = 0; tm < 4; tm++)
                #pragma unroll
                for (int tn = 0; tn < 4; tn++)
                    mma_f16(acc[tm][tn], af[tm], bf[tn]);
        }
    }

    #pragma unroll
    for (int tm = 0; tm < 4; tm++) {
        #pragma unroll
        for (int half_ = 0; half_ < 2; half_++) {
            int m = m0 + mw + tm * 16 + g + half_ * 8;
            if (m >= M) continue;
            size_t obase = 0;
            const float* rbase = nullptr;
            bool valid = true;
            if (EPI == 2) {
                int bw = m / TOK, tt = m % TOK;
                int bb = bw / (NWH * NWW), rem = bw % (NWH * NWW);
                int wh = rem / NWW, ww = rem % NWW;
                int ii = tt / WS, jj = tt % WS;
                int h = wh * WS + ii, w = ww * WS + jj;
                if (h >= IMGH || w >= IMGW) valid = false;
                else { obase = ((size_t)(bb * IMGH + h) * IMGW + w) * CDIM; rbase = R + obase; }
            } else {
                obase = (size_t)m * N;
                if (EPI == 3) rbase = R + obase;
            }
            if (!valid) continue;
            #pragma unroll
            for (int tn = 0; tn < 4; tn++) {
                int n = n0 + nw + tn * 8 + 2 * c;
                float v0 = acc[tm][tn][half_ * 2 + 0] + bias[n];
                float v1 = acc[tm][tn][half_ * 2 + 1] + bias[n + 1];
                if (EPI == 0) {
                    *(__half2*)((__half*)Cc + obase + n) = __floats2half2_rn(v0, v1);
                } else if (EPI == 1) {
                    v0 = 0.5f * v0 * (1.0f + erff(v0 * 0.7071067811865476f));
                    v1 = 0.5f * v1 * (1.0f + erff(v1 * 0.7071067811865476f));
                    *(__half2*)((__half*)Cc + obase + n) = __floats2half2_rn(v0, v1);
                } else {
                    v0 += rbase[n];
                    v1 += rbase[n + 1];
                    *(float2*)((float*)Cc + obase + n) = make_float2(v0, v1);
                }
            }
        }
    }
}

// ---------------- tensor-core windowed attention ----------------
// 1 CTA per (window, head). 256 thr, 8 warps. Tokens padded 196->208.
// QK^T: 13 m-tiles x 26 n-tiles, m16n8k16, bias+softmax in C frags; PV via ldmatrix.trans.
#define TPAD 208
#define QSTR 72          // halfs per Q/K/V row
#define PSTR 216         // halfs per P row
#define AT2_Q  0                          // 208*72*2 = 29952
#define AT2_K  29952
#define AT2_V  59904
#define AT2_P  89856                      // 8 warps * 16*216*2 = 55296
#define AT2_RH 145152                     // 208*16*4 = 13312
#define AT2_RW 158464
#define ATTN_SMEM_BYTES 171776

__global__ __launch_bounds__(256, 1)
void attn_mma_kernel(const __half* __restrict__ qkv,
                     const float* __restrict__ relh,
                     const float* __restrict__ relw,
                     __half* __restrict__ attout) {
    extern __shared__ char smc[];
    __half* Qs = (__half*)(smc + AT2_Q);
    __half* Ks = (__half*)(smc + AT2_K);
    __half* Vs = (__half*)(smc + AT2_V);
    float* RH = (float*)(smc + AT2_RH);
    float* RW = (float*)(smc + AT2_RW);

    int blk = blockIdx.x;
    int bw = blk / NH, nh = blk % NH;
    int tid = threadIdx.x, lane = tid & 31, warp = tid >> 5;
    int g = lane >> 2, c = lane & 3;

    // ---- load q/k/v (tokens 0..195), zero pad rows 196..207 ----
    const __half* base = qkv + (size_t)bw * TOK * QKVN + nh * HD;
    for (int t4 = tid; t4 < TOK * 8; t4 += 256) {
        int t = t4 >> 3, cp = (t4 & 7) * 8;
        const __half* p = base + (size_t)t * QKVN + cp;
        *(uint4*)(Qs + t * QSTR + cp) = *(const uint4*)(p);
        *(uint4*)(Ks + t * QSTR + cp) = *(const uint4*)(p + CDIM);
        *(uint4*)(Vs + t * QSTR + cp) = *(const uint4*)(p + 2 * CDIM);
    }
    for (int i = tid; i < 12 * 9; i += 256) {
        int r = TOK + i / 9, cp = (i % 9) * 8;
        uint4 z = make_uint4(0, 0, 0, 0);
        *(uint4*)(Qs + r * QSTR + cp) = z;
        *(uint4*)(Ks + r * QSTR + cp) = z;
        *(uint4*)(Vs + r * QSTR + cp) = z;
    }
    __syncthreads();

    // ---- decomposed rel-pos: RH[qi][kk], RW[qi][ll] (lanes 0..13 rh, 16..29 rw) ----
    for (int qi = warp; qi < TOK; qi += 8) {
        int i = qi / WS, j = qi % WS;
        const __half2* q2 = (const __half2*)(Qs + qi * QSTR);
        if (lane < WS) {
            const float* tab = relh + (size_t)(i - lane + WS - 1) * HD;
            float a = 0.f;
            #pragma unroll 8
            for (int cp = 0; cp < 32; cp++) {
                float2 qf = __half22float2(q2[cp]);
                float2 tf = *(const float2*)(tab + 2 * cp);
                a = fmaf(qf.x, tf.x, fmaf(qf.y, tf.y, a));
            }
            RH[qi * 16 + lane] = a;
        } else if (lane >= 16 && lane < 16 + WS) {
            int ll = lane - 16;
            const float* tab = relw + (size_t)(j - ll + WS - 1) * HD;
            float a = 0.f;
            #pragma unroll 8
            for (int cp = 0; cp < 32; cp++) {
                float2 qf = __half22float2(q2[cp]);
                float2 tf = *(const float2*)(tab + 2 * cp);
                a = fmaf(qf.x, tf.x, fmaf(qf.y, tf.y, a));
            }
            RW[qi * 16 + ll] = a;
        }
    }
    __syncthreads();

    uint32_t Qs_u = smem_u32(Qs), Ks_u = smem_u32(Ks), Vs_u = smem_u32(Vs);
    __half* Pb = (__half*)(smc + AT2_P) + warp * 16 * PSTR;
    uint32_t Pb_u = smem_u32(Pb);
    const float scale = 0.125f;

    for (int mt = warp; mt < 13; mt += 8) {
        int m0 = mt * 16;
        int qi0 = m0 + g, qi1 = m0 + g + 8;

        // ---- S = Q K^T ----
        float acc[26][4];
        #pragma unroll
        for (int nt = 0; nt < 26; nt++)
            #pragma unroll
            for (int q = 0; q < 4; q++) acc[nt][q] = 0.f;

        #pragma unroll
        for (int ks = 0; ks < 4; ks++) {
            uint32_t af[4];
            ldmatrix_x4(af, Qs_u + (uint32_t)((m0 + (lane & 15)) * QSTR + (lane >> 4) * 8 + ks * 16) * 2);
            #pragma unroll
            for (int nt = 0; nt < 26; nt++) {
                uint32_t bf[2];
                ldmatrix_x2(bf, Ks_u + (uint32_t)((nt * 8 + (lane & 7)) * QSTR + ks * 16 + ((lane >> 3) & 1) * 8) * 2);
                mma_f16(acc[nt], af, bf);
            }
        }

        // ---- bias + softmax (rows g and g+8; quad = lanes sharing g) ----
        float rh0base = 0.f, rw0base = 0.f, rh1base = 0.f, rw1base = 0.f; // unused; per-col lookup below
        float mx0 = -1e30f, mx1 = -1e30f;
        #pragma unroll
        for (int nt = 0; nt < 26; nt++) {
            int n = nt * 8 + 2 * c;
            int n2 = n + 1;
            if (n < TOK) {
                int kk = n / WS, ll = n % WS;
                acc[nt][0] = acc[nt][0] * scale + RH[qi0 * 16 + kk] + RW[qi0 * 16 + ll];
                acc[nt][2] = acc[nt][2] * scale + RH[qi1 * 16 + kk] + RW[qi1 * 16 + ll];
            } else { acc[nt][0] = -1e30f; acc[nt][2] = -1e30f; }
            if (n2 < TOK) {
                int kk = n2 / WS, ll = n2 % WS;
                acc[nt][1] = acc[nt][1] * scale + RH[qi0 * 16 + kk] + RW[qi0 * 16 + ll];
                acc[nt][3] = acc[nt][3] * scale + RH[qi1 * 16 + kk] + RW[qi1 * 16 + ll];
            } else { acc[nt][1] = -1e30f; acc[nt][3] = -1e30f; }
            mx0 = fmaxf(mx0, fmaxf(acc[nt][0], acc[nt][1]));
            mx1 = fmaxf(mx1, fmaxf(acc[nt][2], acc[nt][3]));
        }
        #pragma unroll
        for (int o = 1; o <= 2; o <<= 1) {
            mx0 = fmaxf(mx0, __shfl_xor_sync(0xffffffffu, mx0, o));
            mx1 = fmaxf(mx1, __shfl_xor_sync(0xffffffffu, mx1, o));
        }
        float sum0 = 0.f, sum1 = 0.f;
        #pragma unroll
        for (int nt = 0; nt < 26; nt++) {
            acc[nt][0] = __expf(acc[nt][0] - mx0);
            acc[nt][1] = __expf(acc[nt][1] - mx0);
            acc[nt][2] = __expf(acc[nt][2] - mx1);
            acc[nt][3] = __expf(acc[nt][3] - mx1);
            sum0 += acc[nt][0] + acc[nt][1];
            sum1 += acc[nt][2] + acc[nt][3];
        }
        #pragma unroll
        for (int o = 1; o <= 2; o <<= 1) {
            sum0 += __shfl_xor_sync(0xffffffffu, sum0, o);
            sum1 += __shfl_xor_sync(0xffffffffu, sum1, o);
        }
        float inv0 = __frcp_rn(sum0), inv1 = __frcp_rn(sum1);
        #pragma unroll
        for (int nt = 0; nt < 26; nt++) {
            int col = nt * 8 + 2 * c;
            *(__half2*)(Pb + g * PSTR + col)       = __floats2half2_rn(acc[nt][0] * inv0, acc[nt][1] * inv0);
            *(__half2*)(Pb + (g + 8) * PSTR + col) = __floats2half2_rn(acc[nt][2] * inv1, acc[nt][3] * inv1);
        }
        __syncwarp();

        // ---- O = P V ----
        float acc2[8][4];
        #pragma unroll
        for (int nt = 0; nt < 8; nt++)
            #pragma unroll
            for (int q = 0; q < 4; q++) acc2[nt][q] = 0.f;
        #pragma unroll
        for (int ks = 0; ks < 13; ks++) {
            uint32_t af[4];
            ldmatrix_x4(af, Pb_u + (uint32_t)((lane & 15) * PSTR + (lane >> 4) * 8 + ks * 16) * 2);
            #pragma unroll
            for (int nt = 0; nt < 8; nt++) {
                uint32_t bf[2];
                ldmatrix_x2_trans(bf, Vs_u + (uint32_t)((ks * 16 + (lane & 7) + ((lane >> 3) & 1) * 8) * QSTR + nt * 8) * 2);
                mma_f16(acc2[nt], af, bf);
            }
        }
        if (qi0 < TOK) {
            __half* orow = attout + ((size_t)(bw * TOK + qi0)) * CDIM + nh * HD;
            #pragma unroll
            for (int nt = 0; nt < 8; nt++)
                *(__half2*)(orow + nt * 8 + 2 * c) = __floats2half2_rn(acc2[nt][0], acc2[nt][1]);
        }
        if (qi1 < TOK) {
            __half* orow = attout + ((size_t)(bw * TOK + qi1)) * CDIM + nh * HD;
            #pragma unroll
            for (int nt = 0; nt < 8; nt++)
                *(__half2*)(orow + nt * 8 + 2 * c) = __floats2half2_rn(acc2[nt][2], acc2[nt][3]);
        }
        __syncwarp();
    }
}

// ---------------- launch ----------------
extern "C" void kernel_launch(void* const* d_in, const int* in_sizes, int n_in,
                              void* d_out, int out_size) {
    const float* x       = (const float*)d_in[0];
    const float* ln1_g   = (const float*)d_in[1];
    const float* ln1_b   = (const float*)d_in[2];
    const float* w_qkv   = (const float*)d_in[3];
    const float* b_qkv   = (const float*)d_in[4];
    const float* w_proj  = (const float*)d_in[5];
    const float* b_proj  = (const float*)d_in[6];
    const float* relh    = (const float*)d_in[7];
    const float* relw    = (const float*)d_in[8];
    const float* ln2_g   = (const float*)d_in[9];
    const float* ln2_b   = (const float*)d_in[10];
    const float* w_fc1   = (const float*)d_in[11];
    const float* b_fc1   = (const float*)d_in[12];
    const float* w_fc2   = (const float*)d_in[13];
    const float* b_fc2   = (const float*)d_in[14];
    float* out = (float*)d_out;

    __half *win, *qkv, *att, *yln, *y1, *wqkv, *wproj, *wfc1, *wfc2;
    float *x2;
    cudaGetSymbolAddress((void**)&win, g_win);
    cudaGetSymbolAddress((void**)&qkv, g_qkv);
    cudaGetSymbolAddress((void**)&att, g_att);
    cudaGetSymbolAddress((void**)&x2,  g_x2);
    cudaGetSymbolAddress((void**)&yln, g_yln);
    cudaGetSymbolAddress((void**)&y1,  g_y1);
    cudaGetSymbolAddress((void**)&wqkv,  g_wqkv);
    cudaGetSymbolAddress((void**)&wproj, g_wproj);
    cudaGetSymbolAddress((void**)&wfc1,  g_wfc1);
    cudaGetSymbolAddress((void**)&wfc2,  g_wfc2);

    cudaFuncSetAttribute(attn_mma_kernel, cudaFuncAttributeMaxDynamicSharedMemorySize, ATTN_SMEM_BYTES);
    cudaFuncSetAttribute(hgemm<0>, cudaFuncAttributeMaxDynamicSharedMemorySize, GEMM_SMEM_BYTES);
    cudaFuncSetAttribute(hgemm<1>, cudaFuncAttributeMaxDynamicSharedMemorySize, GEMM_SMEM_BYTES);
    cudaFuncSetAttribute(hgemm<2>, cudaFuncAttributeMaxDynamicSharedMemorySize, GEMM_SMEM_BYTES);
    cudaFuncSetAttribute(hgemm<3>, cudaFuncAttributeMaxDynamicSharedMemorySize, GEMM_SMEM_BYTES);

    // (1) weights -> half2 interleaved
    int wtot = W1T + W2T + W3T + W4T;
    w2h_all_kernel<<<(wtot + 255) / 256, 256>>>(w_qkv, w_proj, w_fc1, w_fc2,
                                                wqkv, wproj, wfc1, wfc2);

    // (2) LN1 + window partition
    ln1_win_kernel<<<(ROWS_WIN * 32 + 255) / 256, 256>>>(x, ln1_g, ln1_b, win);

    // (3) QKV GEMM -> half
    hgemm<0><<<dim3(QKVN / 128, (ROWS_WIN + 127) / 128), 256, GEMM_SMEM_BYTES>>>(
        win, wqkv, b_qkv, nullptr, qkv, ROWS_WIN, QKVN, CDIM);

    // (4) attention (tensor cores)
    attn_mma_kernel<<<BW * NH, 256, ATTN_SMEM_BYTES>>>(qkv, relh, relw, att);

    // (5) proj + window reverse + residual -> f32
    hgemm<2><<<dim3(CDIM / 128, (ROWS_WIN + 127) / 128), 256, GEMM_SMEM_BYTES>>>(
        att, wproj, b_proj, x, x2, ROWS_WIN, CDIM, CDIM);

    // (6) LN2 -> half
    ln2_kernel<<<(ROWS_IMG * 32 + 255) / 256, 256>>>(x2, ln2_g, ln2_b, yln);

    // (7) fc1 + gelu -> half
    hgemm<1><<<dim3(FFN / 128, ROWS_IMG / 128), 256, GEMM_SMEM_BYTES>>>(
        yln, wfc1, b_fc1, nullptr, y1, ROWS_IMG, FFN, CDIM);

    // (8) fc2 + residual -> out f32
    hgemm<3><<<dim3(CDIM / 128, ROWS_IMG / 128), 256, GEMM_SMEM_BYTES>>>(
        y1, wfc2, b_fc2, x2, out, ROWS_IMG, CDIM, FFN);
}

// round 11
// speedup vs baseline: 1.0003x; 1.0003x over previous
#include <cuda_runtime.h>
#include <cuda_fp16.h>
#include <math.h>
#include <stdint.h>

// ---------------- problem constants ----------------
#define BATCH 4
#define IMGH  64
#define IMGW  64
#define CDIM  768
#define WS    14
#define TOK   196
#define NH    12
#define HD    64
#define NWH   5
#define NWW   5
#define BW    100
#define ROWS_WIN 19600
#define ROWS_IMG 16384
#define QKVN  2304
#define FFN   3072

// ---------------- scratch ----------------
__device__ __half g_win[(size_t)ROWS_WIN * CDIM];
__device__ __half g_qkv[(size_t)ROWS_WIN * QKVN];
__device__ __half g_att[(size_t)ROWS_WIN * CDIM];
__device__ float  g_x2 [(size_t)ROWS_IMG * CDIM];
__device__ __half g_yln[(size_t)ROWS_IMG * CDIM];
__device__ __half g_y1 [(size_t)ROWS_IMG * FFN];
__device__ __half g_wqkv[(size_t)CDIM * QKVN];
__device__ __half g_wproj[(size_t)CDIM * CDIM];
__device__ __half g_wfc1[(size_t)CDIM * FFN];
__device__ __half g_wfc2[(size_t)FFN * CDIM];

// ---------------- helpers ----------------
__device__ __forceinline__ uint32_t smem_u32(const void* p) {
    uint32_t a;
    asm("{ .reg .u64 t; cvta.to.shared.u64 t, %1; cvt.u32.u64 %0, t; }" : "=r"(a) : "l"(p));
    return a;
}
__device__ __forceinline__ void cp16(void* sdst, const void* gsrc, int bytes) {
    uint32_t sa = smem_u32(sdst);
    asm volatile("cp.async.cg.shared.global [%0], [%1], 16, %2;" :: "r"(sa), "l"(gsrc), "r"(bytes));
}
#define CP_COMMIT() asm volatile("cp.async.commit_group;")

__device__ __forceinline__ void mma_f16(float c[4], const uint32_t a[4], const uint32_t b[2]) {
    asm volatile(
        "mma.sync.aligned.m16n8k16.row.col.f32.f16.f16.f32 "
        "{%0,%1,%2,%3}, {%4,%5,%6,%7}, {%8,%9}, {%0,%1,%2,%3};"
        : "+f"(c[0]), "+f"(c[1]), "+f"(c[2]), "+f"(c[3])
        : "r"(a[0]), "r"(a[1]), "r"(a[2]), "r"(a[3]), "r"(b[0]), "r"(b[1]));
}
__device__ __forceinline__ void ldmatrix_x4(uint32_t r[4], uint32_t addr) {
    asm volatile("ldmatrix.sync.aligned.m8n8.x4.shared.b16 {%0,%1,%2,%3}, [%4];"
                 : "=r"(r[0]), "=r"(r[1]), "=r"(r[2]), "=r"(r[3]) : "r"(addr));
}
__device__ __forceinline__ void ldmatrix_x2(uint32_t r[2], uint32_t addr) {
    asm volatile("ldmatrix.sync.aligned.m8n8.x2.shared.b16 {%0,%1}, [%2];"
                 : "=r"(r[0]), "=r"(r[1]) : "r"(addr));
}
__device__ __forceinline__ void ldmatrix_x2_trans(uint32_t r[2], uint32_t addr) {
    asm volatile("ldmatrix.sync.aligned.m8n8.x2.trans.shared.b16 {%0,%1}, [%2];"
                 : "=r"(r[0]), "=r"(r[1]) : "r"(addr));
}

// ---------------- all weights -> half2 k-pair interleaved ----------------
#define W1T ((CDIM / 2) * QKVN)
#define W2T ((CDIM / 2) * CDIM)
#define W3T ((CDIM / 2) * FFN)
#define W4T ((FFN / 2) * CDIM)
__global__ void w2h_all_kernel(const float* __restrict__ wq, const float* __restrict__ wp,
                               const float* __restrict__ w1, const float* __restrict__ w2,
                               __half* __restrict__ oq, __half* __restrict__ op,
                               __half* __restrict__ o1, __half* __restrict__ o2) {
    int idx = blockIdx.x * blockDim.x + threadIdx.x;
    const float* in; __half* out; int Nd, local;
    if (idx < W1T)                    { in = wq; out = oq; Nd = QKVN; local = idx; }
    else if (idx < W1T + W2T)         { in = wp; out = op; Nd = CDIM; local = idx - W1T; }
    else if (idx < W1T + W2T + W3T)   { in = w1; out = o1; Nd = FFN;  local = idx - W1T - W2T; }
    else if (idx < W1T + W2T + W3T + W4T) { in = w2; out = o2; Nd = CDIM; local = idx - W1T - W2T - W3T; }
    else return;
    int kp = local / Nd, n = local % Nd;
    float a = in[(size_t)(2 * kp) * Nd + n];
    float b = in[(size_t)(2 * kp + 1) * Nd + n];
    ((__half2*)out)[local] = __floats2half2_rn(a, b);
}

// ---------------- LN1 + window partition -> half ----------------
__global__ void ln1_win_kernel(const float* __restrict__ x,
                               const float* __restrict__ g,
                               const float* __restrict__ b,
                               __half* __restrict__ out_) {
    int warp = (blockIdx.x * blockDim.x + threadIdx.x) >> 5;
    int lane = threadIdx.x & 31;
    if (warp >= ROWS_WIN) return;
    int r = warp;
    int bw = r / TOK, t = r % TOK;
    int bb = bw / (NWH * NWW), rem = bw % (NWH * NWW);
    int wh = rem / NWW, ww = rem % NWW;
    int i = t / WS, j = t % WS;
    int h = wh * WS + i, w = ww * WS + j;
    __half* out = out_ + (size_t)r * CDIM;
    if (h >= IMGH || w >= IMGW) {
        uint2 z = make_uint2(0u, 0u);
        #pragma unroll
        for (int q = 0; q < 6; q++) *(uint2*)(out + lane * 4 + q * 128) = z;
        return;
    }
    const float* row = x + ((size_t)(bb * IMGH + h) * IMGW + w) * CDIM;
    float v[24];
    float s = 0.f;
    #pragma unroll
    for (int q = 0; q < 6; q++) {
        float4 f = *(const float4*)(row + lane * 4 + q * 128);
        v[q*4+0] = f.x; v[q*4+1] = f.y; v[q*4+2] = f.z; v[q*4+3] = f.w;
        s += f.x + f.y + f.z + f.w;
    }
    #pragma unroll
    for (int o = 16; o > 0; o >>= 1) s += __shfl_xor_sync(0xffffffffu, s, o);
    float mean = s * (1.0f / CDIM);
    float ss = 0.f;
    #pragma unroll
    for (int q = 0; q < 24; q++) { float d = v[q] - mean; ss += d * d; }
    #pragma unroll
    for (int o = 16; o > 0; o >>= 1) ss += __shfl_xor_sync(0xffffffffu, ss, o);
    float rstd = rsqrtf(ss * (1.0f / CDIM) + 1e-6f);
    #pragma unroll
    for (int q = 0; q < 6; q++) {
        int c = lane * 4 + q * 128;
        float4 gg = *(const float4*)(g + c);
        float4 bb4 = *(const float4*)(b + c);
        __half2 h0 = __floats2half2_rn((v[q*4+0] - mean) * rstd * gg.x + bb4.x,
                                       (v[q*4+1] - mean) * rstd * gg.y + bb4.y);
        __half2 h1 = __floats2half2_rn((v[q*4+2] - mean) * rstd * gg.z + bb4.z,
                                       (v[q*4+3] - mean) * rstd * gg.w + bb4.w);
        *(__half2*)(out + c) = h0;
        *(__half2*)(out + c + 2) = h1;
    }
}

// ---------------- LN2 -> half ----------------
__global__ void ln2_kernel(const float* __restrict__ x,
                           const float* __restrict__ g,
                           const float* __restrict__ b,
                           __half* __restrict__ out_) {
    int warp = (blockIdx.x * blockDim.x + threadIdx.x) >> 5;
    int lane = threadIdx.x & 31;
    if (warp >= ROWS_IMG) return;
    const float* row = x + (size_t)warp * CDIM;
    __half* out = out_ + (size_t)warp * CDIM;
    float v[24];
    float s = 0.f;
    #pragma unroll
    for (int q = 0; q < 6; q++) {
        float4 f = *(const float4*)(row + lane * 4 + q * 128);
        v[q*4+0] = f.x; v[q*4+1] = f.y; v[q*4+2] = f.z; v[q*4+3] = f.w;
        s += f.x + f.y + f.z + f.w;
    }
    #pragma unroll
    for (int o = 16; o > 0; o >>= 1) s += __shfl_xor_sync(0xffffffffu, s, o);
    float mean = s * (1.0f / CDIM);
    float ss = 0.f;
    #pragma unroll
    for (int q = 0; q < 24; q++) { float d = v[q] - mean; ss += d * d; }
    #pragma unroll
    for (int o = 16; o > 0; o >>= 1) ss += __shfl_xor_sync(0xffffffffu, ss, o);
    float rstd = rsqrtf(ss * (1.0f / CDIM) + 1e-6f);
    #pragma unroll
    for (int q = 0; q < 6; q++) {
        int c = lane * 4 + q * 128;
        float4 gg = *(const float4*)(g + c);
        float4 bb4 = *(const float4*)(b + c);
        __half2 h0 = __floats2half2_rn((v[q*4+0] - mean) * rstd * gg.x + bb4.x,
                                       (v[q*4+1] - mean) * rstd * gg.y + bb4.y);
        __half2 h1 = __floats2half2_rn((v[q*4+2] - mean) * rstd * gg.z + bb4.z,
                                       (v[q*4+3] - mean) * rstd * gg.w + bb4.w);
        *(__half2*)(out + c) = h0;
        *(__half2*)(out + c + 2) = h1;
    }
}

// ---------------- FP16 mma.sync GEMM (k-slab 64, 3-stage, single-sync) ----------------
#define ASTRH 72
#define BSTR2 136
#define A_STAGE_B (128 * ASTRH * 2)
#define B_STAGE_B (32 * BSTR2 * 4)
#define NSTAGE 3
#define GEMM_SMEM_BYTES (NSTAGE * (A_STAGE_B + B_STAGE_B))

template<int EPI>
__global__ __launch_bounds__(256, 2)
void hgemm(const __half* __restrict__ A, const __half* __restrict__ B2,
           const float* __restrict__ bias, const float* __restrict__ R,
           void* __restrict__ Cc, int M, int N, int K) {
    extern __shared__ char smc[];
    __half* As = (__half*)smc;
    __half2* Bs = (__half2*)(smc + NSTAGE * A_STAGE_B);
    uint32_t As_u32 = smem_u32(As);

    int tid = threadIdx.x, wid = tid >> 5, lane = tid & 31;
    int g = lane >> 2, c = lane & 3;
    int mw = (wid >> 2) * 64, nw = (wid & 3) * 32;
    int m0 = blockIdx.y * 128, n0 = blockIdx.x * 128;

    float acc[4][4][4];
    #pragma unroll
    for (int i = 0; i < 4; i++)
        #pragma unroll
        for (int j = 0; j < 4; j++)
            #pragma unroll
            for (int q = 0; q < 4; q++) acc[i][j][q] = 0.f;

    int arow = tid >> 2, achk = (tid & 3) * 16;
    int bkrow = tid >> 3, bseg = (tid & 7) * 16;

    uint32_t a_lm_off = (uint32_t)((mw + (lane & 15)) * ASTRH + (lane >> 4) * 8) * 2;

    auto loadStage = [&](int t) {
        int st = t % NSTAGE;
        __half* Ad = As + (size_t)st * 128 * ASTRH;
        #pragma unroll
        for (int p = 0; p < 2; p++) {
            int r = arow + p * 64;
            int m = m0 + r;
            bool v = m < M;
            const __half* src = v ? (A + (size_t)m * K + t * 64 + achk) : A;
            cp16(Ad + r * ASTRH + achk,     src,             v ? 16 : 0);
            cp16(Ad + r * ASTRH + achk + 8, v ? src + 8 : A, v ? 16 : 0);
        }
        __half2* Bd = Bs + (size_t)st * 32 * BSTR2;
        const __half2* bsrc = (const __half2*)B2 + (size_t)(t * 32 + bkrow) * N + n0 + bseg;
        #pragma unroll
        for (int i = 0; i < 4; i++)
            cp16(Bd + bkrow * BSTR2 + bseg + 4 * i, bsrc + 4 * i, 16);
        CP_COMMIT();
    };

    int nk = K / 64;
    #pragma unroll
    for (int t = 0; t < NSTAGE - 1; t++) loadStage(t);

    for (int t = 0; t < nk; t++) {
        asm volatile("cp.async.wait_group %0;" :: "n"(NSTAGE - 2) : "memory");
        __syncthreads();
        if (t + NSTAGE - 1 < nk) loadStage(t + NSTAGE - 1);
        else CP_COMMIT();
        uint32_t a_base = As_u32 + (uint32_t)((t % NSTAGE) * A_STAGE_B) + a_lm_off;
        const __half2* b_s = Bs + (size_t)(t % NSTAGE) * 32 * BSTR2;
        #pragma unroll
        for (int kk = 0; kk < 4; kk++) {
            uint32_t af[4][4], bf[4][2];
            #pragma unroll
            for (int tm = 0; tm < 4; tm++)
                ldmatrix_x4(af[tm], a_base + (uint32_t)(tm * 16 * ASTRH + kk * 16) * 2);
            #pragma unroll
            for (int tn = 0; tn < 4; tn++) {
                const __half2* bp = b_s + (kk * 8 + c) * BSTR2 + nw + tn * 8 + g;
                bf[tn][0] = *(const uint32_t*)(bp);
                bf[tn][1] = *(const uint32_t*)(bp + 4 * BSTR2);
            }
            #pragma unroll
            for (int tm = 0; tm < 4; tm++)
                #pragma unroll
                for (int tn = 0; tn < 4; tn++)
                    mma_f16(acc[tm][tn], af[tm], bf[tn]);
        }
    }

    #pragma unroll
    for (int tm = 0; tm < 4; tm++) {
        #pragma unroll
        for (int half_ = 0; half_ < 2; half_++) {
            int m = m0 + mw + tm * 16 + g + half_ * 8;
            if (m >= M) continue;
            size_t obase = 0;
            const float* rbase = nullptr;
            bool valid = true;
            if (EPI == 2) {
                int bw = m / TOK, tt = m % TOK;
                int bb = bw / (NWH * NWW), rem = bw % (NWH * NWW);
                int wh = rem / NWW, ww = rem % NWW;
                int ii = tt / WS, jj = tt % WS;
                int h = wh * WS + ii, w = ww * WS + jj;
                if (h >= IMGH || w >= IMGW) valid = false;
                else { obase = ((size_t)(bb * IMGH + h) * IMGW + w) * CDIM; rbase = R + obase; }
            } else {
                obase = (size_t)m * N;
                if (EPI == 3) rbase = R + obase;
            }
            if (!valid) continue;
            #pragma unroll
            for (int tn = 0; tn < 4; tn++) {
                int n = n0 + nw + tn * 8 + 2 * c;
                float v0 = acc[tm][tn][half_ * 2 + 0] + bias[n];
                float v1 = acc[tm][tn][half_ * 2 + 1] + bias[n + 1];
                if (EPI == 0) {
                    *(__half2*)((__half*)Cc + obase + n) = __floats2half2_rn(v0, v1);
                } else if (EPI == 1) {
                    v0 = 0.5f * v0 * (1.0f + erff(v0 * 0.7071067811865476f));
                    v1 = 0.5f * v1 * (1.0f + erff(v1 * 0.7071067811865476f));
                    *(__half2*)((__half*)Cc + obase + n) = __floats2half2_rn(v0, v1);
                } else {
                    v0 += rbase[n];
                    v1 += rbase[n + 1];
                    *(float2*)((float*)Cc + obase + n) = make_float2(v0, v1);
                }
            }
        }
    }
}

// ---------------- tensor-core windowed attention ----------------
// 1 CTA per (window, head). 256 thr, 8 warps. Tokens padded 196->208.
// QK^T: 13 m-tiles x 26 n-tiles, m16n8k16, bias+softmax in C frags; PV via ldmatrix.trans.
#define TPAD 208
#define QSTR 72          // halfs per Q/K/V row
#define PSTR 216         // halfs per P row
#define AT2_Q  0                          // 208*72*2 = 29952
#define AT2_K  29952
#define AT2_V  59904
#define AT2_P  89856                      // 8 warps * 16*216*2 = 55296
#define AT2_RH 145152                     // 208*16*4 = 13312
#define AT2_RW 158464
#define ATTN_SMEM_BYTES 171776

__global__ __launch_bounds__(256, 1)
void attn_mma_kernel(const __half* __restrict__ qkv,
                     const float* __restrict__ relh,
                     const float* __restrict__ relw,
                     __half* __restrict__ attout) {
    extern __shared__ char smc[];
    __half* Qs = (__half*)(smc + AT2_Q);
    __half* Ks = (__half*)(smc + AT2_K);
    __half* Vs = (__half*)(smc + AT2_V);
    float* RH = (float*)(smc + AT2_RH);
    float* RW = (float*)(smc + AT2_RW);

    int blk = blockIdx.x;
    int bw = blk / NH, nh = blk % NH;
    int tid = threadIdx.x, lane = tid & 31, warp = tid >> 5;
    int g = lane >> 2, c = lane & 3;

    // ---- load q/k/v (tokens 0..195), zero pad rows 196..207 ----
    const __half* base = qkv + (size_t)bw * TOK * QKVN + nh * HD;
    for (int t4 = tid; t4 < TOK * 8; t4 += 256) {
        int t = t4 >> 3, cp = (t4 & 7) * 8;
        const __half* p = base + (size_t)t * QKVN + cp;
        *(uint4*)(Qs + t * QSTR + cp) = *(const uint4*)(p);
        *(uint4*)(Ks + t * QSTR + cp) = *(const uint4*)(p + CDIM);
        *(uint4*)(Vs + t * QSTR + cp) = *(const uint4*)(p + 2 * CDIM);
    }
    for (int i = tid; i < 12 * 9; i += 256) {
        int r = TOK + i / 9, cp = (i % 9) * 8;
        uint4 z = make_uint4(0, 0, 0, 0);
        *(uint4*)(Qs + r * QSTR + cp) = z;
        *(uint4*)(Ks + r * QSTR + cp) = z;
        *(uint4*)(Vs + r * QSTR + cp) = z;
    }
    __syncthreads();

    // ---- decomposed rel-pos: RH[qi][kk], RW[qi][ll] (lanes 0..13 rh, 16..29 rw) ----
    for (int qi = warp; qi < TOK; qi += 8) {
        int i = qi / WS, j = qi % WS;
        const __half2* q2 = (const __half2*)(Qs + qi * QSTR);
        if (lane < WS) {
            const float* tab = relh + (size_t)(i - lane + WS - 1) * HD;
            float a = 0.f;
            #pragma unroll 8
            for (int cp = 0; cp < 32; cp++) {
                float2 qf = __half22float2(q2[cp]);
                float2 tf = *(const float2*)(tab + 2 * cp);
                a = fmaf(qf.x, tf.x, fmaf(qf.y, tf.y, a));
            }
            RH[qi * 16 + lane] = a;
        } else if (lane >= 16 && lane < 16 + WS) {
            int ll = lane - 16;
            const float* tab = relw + (size_t)(j - ll + WS - 1) * HD;
            float a = 0.f;
            #pragma unroll 8
            for (int cp = 0; cp < 32; cp++) {
                float2 qf = __half22float2(q2[cp]);
                float2 tf = *(const float2*)(tab + 2 * cp);
                a = fmaf(qf.x, tf.x, fmaf(qf.y, tf.y, a));
            }
            RW[qi * 16 + ll] = a;
        }
    }
    __syncthreads();

    uint32_t Qs_u = smem_u32(Qs), Ks_u = smem_u32(Ks), Vs_u = smem_u32(Vs);
    __half* Pb = (__half*)(smc + AT2_P) + warp * 16 * PSTR;
    uint32_t Pb_u = smem_u32(Pb);
    const float scale = 0.125f;

    for (int mt = warp; mt < 13; mt += 8) {
        int m0 = mt * 16;
        int qi0 = m0 + g, qi1 = m0 + g + 8;

        // ---- S = Q K^T ----
        float acc[26][4];
        #pragma unroll
        for (int nt = 0; nt < 26; nt++)
            #pragma unroll
            for (int q = 0; q < 4; q++) acc[nt][q] = 0.f;

        #pragma unroll
        for (int ks = 0; ks < 4; ks++) {
            uint32_t af[4];
            ldmatrix_x4(af, Qs_u + (uint32_t)((m0 + (lane & 15)) * QSTR + (lane >> 4) * 8 + ks * 16) * 2);
            #pragma unroll
            for (int nt = 0; nt < 26; nt++) {
                uint32_t bf[2];
                ldmatrix_x2(bf, Ks_u + (uint32_t)((nt * 8 + (lane & 7)) * QSTR + ks * 16 + ((lane >> 3) & 1) * 8) * 2);
                mma_f16(acc[nt], af, bf);
            }
        }

        // ---- bias + softmax (rows g and g+8; quad = lanes sharing g) ----
        float rh0base = 0.f, rw0base = 0.f, rh1base = 0.f, rw1base = 0.f; // unused; per-col lookup below
        float mx0 = -1e30f, mx1 = -1e30f;
        #pragma unroll
        for (int nt = 0; nt < 26; nt++) {
            int n = nt * 8 + 2 * c;
            int n2 = n + 1;
            if (n < TOK) {
                int kk = n / WS, ll = n % WS;
                acc[nt][0] = acc[nt][0] * scale + RH[qi0 * 16 + kk] + RW[qi0 * 16 + ll];
                acc[nt][2] = acc[nt][2] * scale + RH[qi1 * 16 + kk] + RW[qi1 * 16 + ll];
            } else { acc[nt][0] = -1e30f; acc[nt][2] = -1e30f; }
            if (n2 < TOK) {
                int kk = n2 / WS, ll = n2 % WS;
                acc[nt][1] = acc[nt][1] * scale + RH[qi0 * 16 + kk] + RW[qi0 * 16 + ll];
                acc[nt][3] = acc[nt][3] * scale + RH[qi1 * 16 + kk] + RW[qi1 * 16 + ll];
            } else { acc[nt][1] = -1e30f; acc[nt][3] = -1e30f; }
            mx0 = fmaxf(mx0, fmaxf(acc[nt][0], acc[nt][1]));
            mx1 = fmaxf(mx1, fmaxf(acc[nt][2], acc[nt][3]));
        }
        #pragma unroll
        for (int o = 1; o <= 2; o <<= 1) {
            mx0 = fmaxf(mx0, __shfl_xor_sync(0xffffffffu, mx0, o));
            mx1 = fmaxf(mx1, __shfl_xor_sync(0xffffffffu, mx1, o));
        }
        float sum0 = 0.f, sum1 = 0.f;
        #pragma unroll
        for (int nt = 0; nt < 26; nt++) {
            acc[nt][0] = __expf(acc[nt][0] - mx0);
            acc[nt][1] = __expf(acc[nt][1] - mx0);
            acc[nt][2] = __expf(acc[nt][2] - mx1);
            acc[nt][3] = __expf(acc[nt][3] - mx1);
            sum0 += acc[nt][0] + acc[nt][1];
            sum1 += acc[nt][2] + acc[nt][3];
        }
        #pragma unroll
        for (int o = 1; o <= 2; o <<= 1) {
            sum0 += __shfl_xor_sync(0xffffffffu, sum0, o);
            sum1 += __shfl_xor_sync(0xffffffffu, sum1, o);
        }
        float inv0 = __frcp_rn(sum0), inv1 = __frcp_rn(sum1);
        #pragma unroll
        for (int nt = 0; nt < 26; nt++) {
            int col = nt * 8 + 2 * c;
            *(__half2*)(Pb + g * PSTR + col)       = __floats2half2_rn(acc[nt][0] * inv0, acc[nt][1] * inv0);
            *(__half2*)(Pb + (g + 8) * PSTR + col) = __floats2half2_rn(acc[nt][2] * inv1, acc[nt][3] * inv1);
        }
        __syncwarp();

        // ---- O = P V ----
        float acc2[8][4];
        #pragma unroll
        for (int nt = 0; nt < 8; nt++)
            #pragma unroll
            for (int q = 0; q < 4; q++) acc2[nt][q] = 0.f;
        #pragma unroll
        for (int ks = 0; ks < 13; ks++) {
            uint32_t af[4];
            ldmatrix_x4(af, Pb_u + (uint32_t)((lane & 15) * PSTR + (lane >> 4) * 8 + ks * 16) * 2);
            #pragma unroll
            for (int nt = 0; nt < 8; nt++) {
                uint32_t bf[2];
                ldmatrix_x2_trans(bf, Vs_u + (uint32_t)((ks * 16 + (lane & 7) + ((lane >> 3) & 1) * 8) * QSTR + nt * 8) * 2);
                mma_f16(acc2[nt], af, bf);
            }
        }
        if (qi0 < TOK) {
            __half* orow = attout + ((size_t)(bw * TOK + qi0)) * CDIM + nh * HD;
            #pragma unroll
            for (int nt = 0; nt < 8; nt++)
                *(__half2*)(orow + nt * 8 + 2 * c) = __floats2half2_rn(acc2[nt][0], acc2[nt][1]);
        }
        if (qi1 < TOK) {
            __half* orow = attout + ((size_t)(bw * TOK + qi1)) * CDIM + nh * HD;
            #pragma unroll
            for (int nt = 0; nt < 8; nt++)
                *(__half2*)(orow + nt * 8 + 2 * c) = __floats2half2_rn(acc2[nt][2], acc2[nt][3]);
        }
        __syncwarp();
    }
}

// ---------------- launch ----------------
extern "C" void kernel_launch(void* const* d_in, const int* in_sizes, int n_in,
                              void* d_out, int out_size) {
    const float* x       = (const float*)d_in[0];
    const float* ln1_g   = (const float*)d_in[1];
    const float* ln1_b   = (const float*)d_in[2];
    const float* w_qkv   = (const float*)d_in[3];
    const float* b_qkv   = (const float*)d_in[4];
    const float* w_proj  = (const float*)d_in[5];
    const float* b_proj  = (const float*)d_in[6];
    const float* relh    = (const float*)d_in[7];
    const float* relw    = (const float*)d_in[8];
    const float* ln2_g   = (const float*)d_in[9];
    const float* ln2_b   = (const float*)d_in[10];
    const float* w_fc1   = (const float*)d_in[11];
    const float* b_fc1   = (const float*)d_in[12];
    const float* w_fc2   = (const float*)d_in[13];
    const float* b_fc2   = (const float*)d_in[14];
    float* out = (float*)d_out;

    __half *win, *qkv, *att, *yln, *y1, *wqkv, *wproj, *wfc1, *wfc2;
    float *x2;
    cudaGetSymbolAddress((void**)&win, g_win);
    cudaGetSymbolAddress((void**)&qkv, g_qkv);
    cudaGetSymbolAddress((void**)&att, g_att);
    cudaGetSymbolAddress((void**)&x2,  g_x2);
    cudaGetSymbolAddress((void**)&yln, g_yln);
    cudaGetSymbolAddress((void**)&y1,  g_y1);
    cudaGetSymbolAddress((void**)&wqkv,  g_wqkv);
    cudaGetSymbolAddress((void**)&wproj, g_wproj);
    cudaGetSymbolAddress((void**)&wfc1,  g_wfc1);
    cudaGetSymbolAddress((void**)&wfc2,  g_wfc2);

    cudaFuncSetAttribute(attn_mma_kernel, cudaFuncAttributeMaxDynamicSharedMemorySize, ATTN_SMEM_BYTES);
    cudaFuncSetAttribute(hgemm<0>, cudaFuncAttributeMaxDynamicSharedMemorySize, GEMM_SMEM_BYTES);
    cudaFuncSetAttribute(hgemm<1>, cudaFuncAttributeMaxDynamicSharedMemorySize, GEMM_SMEM_BYTES);
    cudaFuncSetAttribute(hgemm<2>, cudaFuncAttributeMaxDynamicSharedMemorySize, GEMM_SMEM_BYTES);
    cudaFuncSetAttribute(hgemm<3>, cudaFuncAttributeMaxDynamicSharedMemorySize, GEMM_SMEM_BYTES);

    // (1) weights -> half2 interleaved
    int wtot = W1T + W2T + W3T + W4T;
    w2h_all_kernel<<<(wtot + 255) / 256, 256>>>(w_qkv, w_proj, w_fc1, w_fc2,
                                                wqkv, wproj, wfc1, wfc2);

    // (2) LN1 + window partition
    ln1_win_kernel<<<(ROWS_WIN * 32 + 255) / 256, 256>>>(x, ln1_g, ln1_b, win);

    // (3) QKV GEMM -> half
    hgemm<0><<<dim3(QKVN / 128, (ROWS_WIN + 127) / 128), 256, GEMM_SMEM_BYTES>>>(
        win, wqkv, b_qkv, nullptr, qkv, ROWS_WIN, QKVN, CDIM);

    // (4) attention (tensor cores)
    attn_mma_kernel<<<BW * NH, 256, ATTN_SMEM_BYTES>>>(qkv, relh, relw, att);

    // (5) proj + window reverse + residual -> f32
    hgemm<2><<<dim3(CDIM / 128, (ROWS_WIN + 127) / 128), 256, GEMM_SMEM_BYTES>>>(
        att, wproj, b_proj, x, x2, ROWS_WIN, CDIM, CDIM);

    // (6) LN2 -> half
    ln2_kernel<<<(ROWS_IMG * 32 + 255) / 256, 256>>>(x2, ln2_g, ln2_b, yln);

    // (7) fc1 + gelu -> half
    hgemm<1><<<dim3(FFN / 128, ROWS_IMG / 128), 256, GEMM_SMEM_BYTES>>>(
        yln, wfc1, b_fc1, nullptr, y1, ROWS_IMG, FFN, CDIM);

    // (8) fc2 + residual -> out f32
    hgemm<3><<<dim3(CDIM / 128, ROWS_IMG / 128), 256, GEMM_SMEM_BYTES>>>(
        y1, wfc2, b_fc2, x2, out, ROWS_IMG, CDIM, FFN);
}